// round 2
// baseline (speedup 1.0000x reference)
#include <cuda_runtime.h>
#include <cuda_bf16.h>
#include <math.h>

// Problem constants
#define N_NODES 100000
#define N_EDGES 1600000
#define E_TOT   (N_EDGES + N_NODES)   // with self loops
#define IN_F    67
#define H1      10
#define C1      8
#define F1      (H1 * C1)             // 80

// -------- scratch (static device globals; no allocation) --------
__device__ float g_h1[N_NODES * F1];     // layer1 transformed features
__device__ float g_as1[N_NODES * H1];    // a_src layer1
__device__ float g_ad1[N_NODES * H1];    // a_dst layer1
__device__ float g_m1[N_NODES * H1];     // segment max layer1
__device__ float g_d1[N_NODES * H1];     // segment denom layer1
__device__ float g_o1[N_NODES * F1];     // layer1 aggregated output
__device__ float g_h2[N_NODES];          // layer2 transformed (scalar)
__device__ float g_as2[N_NODES];
__device__ float g_ad2[N_NODES];
__device__ float g_m2[N_NODES];
__device__ float g_d2[N_NODES];
__device__ int   g_is64;                 // edge_index dtype flag

__device__ __forceinline__ void atomicMaxF(float* addr, float val) {
    if (val >= 0.0f) atomicMax((int*)addr, __float_as_int(val));
    else             atomicMin((unsigned int*)addr, __float_as_uint(val));
}

__device__ __forceinline__ float lrelu(float x) { return x > 0.0f ? x : 0.2f * x; }

// -------- K-1: detect edge_index dtype (int64 vs int32) --------
// If int64 little-endian with values < 2^31, every odd 32-bit word is 0.
__global__ void k_detect(const int* __restrict__ ei32) {
    if (threadIdx.x == 0 && blockIdx.x == 0) {
        bool is64 = true;
        #pragma unroll
        for (int i = 1; i < 16; i += 2) if (ei32[i] != 0) is64 = false;
        g_is64 = is64 ? 1 : 0;
    }
}

// -------- edge helpers --------
__device__ __forceinline__ void edge_sd(const void* __restrict__ ei, int e, int& s, int& d) {
    if (e < N_EDGES) {
        if (g_is64) {
            const long long* p = (const long long*)ei;
            s = (int)p[e]; d = (int)p[N_EDGES + e];
        } else {
            const int* p = (const int*)ei;
            s = p[e]; d = p[N_EDGES + e];
        }
        // safety clamp (should never trigger once dtype detection is right)
        if ((unsigned)s >= N_NODES) s = 0;
        if ((unsigned)d >= N_NODES) d = 0;
    } else {
        s = e - N_EDGES; d = s;
    }
}

// -------- K0: init scratch --------
__global__ void k_init() {
    int i = blockIdx.x * blockDim.x + threadIdx.x;
    int stride = gridDim.x * blockDim.x;
    const float NEG_INF = -__int_as_float(0x7f800000);
    for (int j = i; j < N_NODES * H1; j += stride) { g_m1[j] = NEG_INF; g_d1[j] = 0.0f; }
    for (int j = i; j < N_NODES * F1; j += stride) { g_o1[j] = 0.0f; }
    for (int j = i; j < N_NODES; j += stride)      { g_m2[j] = NEG_INF; g_d2[j] = 0.0f; }
}

// -------- K1: h1 = x @ W1 ; a_src1/a_dst1 per node --------
// one block of 80 threads per node
__global__ void k_gemm1(const float* __restrict__ x, const float* __restrict__ W1,
                        const float* __restrict__ att_src1, const float* __restrict__ att_dst1) {
    __shared__ float xs[IN_F];
    __shared__ float ps[F1], pd[F1];
    int n = blockIdx.x;
    int t = threadIdx.x;      // 0..79, head = t/8, channel = t%8
    if (t < IN_F) xs[t] = x[n * IN_F + t];
    __syncthreads();
    float acc = 0.0f;
    #pragma unroll 1
    for (int k = 0; k < IN_F; k++) acc = fmaf(xs[k], W1[k * F1 + t], acc);
    g_h1[n * F1 + t] = acc;
    ps[t] = acc * att_src1[t];
    pd[t] = acc * att_dst1[t];
    __syncthreads();
    if (t < H1) {
        float ss = 0.0f, sd = 0.0f;
        #pragma unroll
        for (int c = 0; c < C1; c++) { ss += ps[t * C1 + c]; sd += pd[t * C1 + c]; }
        g_as1[n * H1 + t] = ss;
        g_ad1[n * H1 + t] = sd;
    }
}

// -------- K2: layer1 segment max (thread per edge-head) --------
__global__ void k_max1(const void* __restrict__ ei) {
    long long tid = (long long)blockIdx.x * blockDim.x + threadIdx.x;
    if (tid >= (long long)E_TOT * H1) return;
    int e = (int)(tid / H1), h = (int)(tid % H1);
    int s, d; edge_sd(ei, e, s, d);
    float ev = lrelu(g_as1[s * H1 + h] + g_ad1[d * H1 + h]);
    atomicMaxF(&g_m1[d * H1 + h], ev);
}

// -------- K3: layer1 sum exp --------
__global__ void k_sum1(const void* __restrict__ ei) {
    long long tid = (long long)blockIdx.x * blockDim.x + threadIdx.x;
    if (tid >= (long long)E_TOT * H1) return;
    int e = (int)(tid / H1), h = (int)(tid % H1);
    int s, d; edge_sd(ei, e, s, d);
    float ev = lrelu(g_as1[s * H1 + h] + g_ad1[d * H1 + h]);
    float ex = __expf(ev - g_m1[d * H1 + h]);
    atomicAdd(&g_d1[d * H1 + h], ex);
}

// -------- K4: layer1 message scatter (thread per edge-head, 8 channels each) --------
__global__ void k_msg1(const void* __restrict__ ei) {
    long long tid = (long long)blockIdx.x * blockDim.x + threadIdx.x;
    if (tid >= (long long)E_TOT * H1) return;
    int e = (int)(tid / H1), h = (int)(tid % H1);
    int s, d; edge_sd(ei, e, s, d);
    float ev = lrelu(g_as1[s * H1 + h] + g_ad1[d * H1 + h]);
    float alpha = __expf(ev - g_m1[d * H1 + h]) / g_d1[d * H1 + h];
    const float4* hp = (const float4*)&g_h1[s * F1 + h * C1];
    float4 v0 = hp[0], v1 = hp[1];
    float* op = &g_o1[d * F1 + h * C1];
    atomicAdd(op + 0, v0.x * alpha);
    atomicAdd(op + 1, v0.y * alpha);
    atomicAdd(op + 2, v0.z * alpha);
    atomicAdd(op + 3, v0.w * alpha);
    atomicAdd(op + 4, v1.x * alpha);
    atomicAdd(op + 5, v1.y * alpha);
    atomicAdd(op + 6, v1.z * alpha);
    atomicAdd(op + 7, v1.w * alpha);
}

// -------- K5: bias + ELU + layer2 GEMM (80->1) + a_src2/a_dst2 + init out --------
// warp per node
__global__ void k_layer2_prep(const float* __restrict__ b1, const float* __restrict__ W2,
                              const float* __restrict__ att_src2, const float* __restrict__ att_dst2,
                              const float* __restrict__ b2, float* __restrict__ out) {
    int warp = (blockIdx.x * blockDim.x + threadIdx.x) >> 5;
    int lane = threadIdx.x & 31;
    if (warp >= N_NODES) return;
    float acc = 0.0f;
    for (int f = lane; f < F1; f += 32) {
        float v = g_o1[warp * F1 + f] + b1[f];
        v = v > 0.0f ? v : (expf(v) - 1.0f);   // ELU
        acc = fmaf(v, W2[f], acc);
    }
    #pragma unroll
    for (int o = 16; o > 0; o >>= 1) acc += __shfl_down_sync(0xffffffffu, acc, o);
    if (lane == 0) {
        g_h2[warp]  = acc;
        g_as2[warp] = acc * att_src2[0];
        g_ad2[warp] = acc * att_dst2[0];
        out[warp]   = b2[0];
    }
}

// -------- K6: layer2 segment max (thread per edge) --------
__global__ void k_max2(const void* __restrict__ ei) {
    int e = blockIdx.x * blockDim.x + threadIdx.x;
    if (e >= E_TOT) return;
    int s, d; edge_sd(ei, e, s, d);
    float ev = lrelu(g_as2[s] + g_ad2[d]);
    atomicMaxF(&g_m2[d], ev);
}

// -------- K7: layer2 sum exp --------
__global__ void k_sum2(const void* __restrict__ ei) {
    int e = blockIdx.x * blockDim.x + threadIdx.x;
    if (e >= E_TOT) return;
    int s, d; edge_sd(ei, e, s, d);
    float ev = lrelu(g_as2[s] + g_ad2[d]);
    atomicAdd(&g_d2[d], __expf(ev - g_m2[d]));
}

// -------- K8: layer2 message scatter --------
__global__ void k_msg2(const void* __restrict__ ei, float* __restrict__ out) {
    int e = blockIdx.x * blockDim.x + threadIdx.x;
    if (e >= E_TOT) return;
    int s, d; edge_sd(ei, e, s, d);
    float ev = lrelu(g_as2[s] + g_ad2[d]);
    float alpha = __expf(ev - g_m2[d]) / g_d2[d];
    atomicAdd(&out[d], g_h2[s] * alpha);
}

extern "C" void kernel_launch(void* const* d_in, const int* in_sizes, int n_in,
                              void* d_out, int out_size) {
    const float* x    = (const float*)d_in[0];
    const void*  ei   = d_in[1];
    const float* W1   = (const float*)d_in[2];
    const float* as1  = (const float*)d_in[3];
    const float* ad1  = (const float*)d_in[4];
    const float* b1   = (const float*)d_in[5];
    const float* W2   = (const float*)d_in[6];
    const float* as2  = (const float*)d_in[7];
    const float* ad2  = (const float*)d_in[8];
    const float* b2   = (const float*)d_in[9];
    float* out = (float*)d_out;

    k_detect<<<1, 32>>>((const int*)ei);
    k_init<<<1184, 256>>>();
    k_gemm1<<<N_NODES, 80>>>(x, W1, as1, ad1);

    long long eh = (long long)E_TOT * H1;
    int blk_eh = (int)((eh + 255) / 256);
    k_max1<<<blk_eh, 256>>>(ei);
    k_sum1<<<blk_eh, 256>>>(ei);
    k_msg1<<<blk_eh, 256>>>(ei);

    int blk_n = (N_NODES * 32 + 255) / 256;
    k_layer2_prep<<<blk_n, 256>>>(b1, W2, as2, ad2, b2, out);

    int blk_e = (E_TOT + 255) / 256;
    k_max2<<<blk_e, 256>>>(ei);
    k_sum2<<<blk_e, 256>>>(ei);
    k_msg2<<<blk_e, 256>>>(ei, out);
}

// round 3
// speedup vs baseline: 2.4615x; 2.4615x over previous
#include <cuda_runtime.h>
#include <cuda_bf16.h>
#include <math.h>

// Problem constants
#define N_NODES 100000
#define N_EDGES 1600000
#define E_TOT   (N_EDGES + N_NODES)   // with self loops
#define IN_F    67
#define H1      10
#define C1      8
#define F1      (H1 * C1)             // 80
#define EH_TOT  ((long long)E_TOT * H1)

// -------- scratch (static device globals; no allocation) --------
__device__ float g_h1[N_NODES * F1];     // layer1 transformed features
__device__ float g_as1[N_NODES * H1];    // a_src layer1
__device__ float g_ad1[N_NODES * H1];    // a_dst layer1
__device__ float g_d1[N_NODES * H1];     // segment denom layer1
__device__ float g_o1[N_NODES * F1];     // layer1 aggregated output
__device__ float g_ex[E_TOT * H1];       // cached exp values (layer1); reused for layer2
__device__ float g_h2[N_NODES];          // layer2 transformed (scalar)
__device__ float g_as2[N_NODES];
__device__ float g_ad2[N_NODES];
__device__ float g_d2[N_NODES];
__device__ int   g_is64;                 // edge_index dtype flag

__device__ __forceinline__ float lrelu(float x) { return x > 0.0f ? x : 0.2f * x; }

__device__ __forceinline__ void redAdd4(float* p, float a, float b, float c, float d) {
    asm volatile("red.global.add.v4.f32 [%0], {%1, %2, %3, %4};"
                 :: "l"(p), "f"(a), "f"(b), "f"(c), "f"(d) : "memory");
}

// -------- K-1: detect edge_index dtype (int64 vs int32) --------
__global__ void k_detect(const int* __restrict__ ei32) {
    if (threadIdx.x == 0 && blockIdx.x == 0) {
        bool is64 = true;
        #pragma unroll
        for (int i = 1; i < 16; i += 2) if (ei32[i] != 0) is64 = false;
        g_is64 = is64 ? 1 : 0;
    }
}

// -------- edge helpers --------
__device__ __forceinline__ void edge_sd(const void* __restrict__ ei, int e, int& s, int& d) {
    if (e < N_EDGES) {
        if (g_is64) {
            const long long* p = (const long long*)ei;
            s = (int)p[e]; d = (int)p[N_EDGES + e];
        } else {
            const int* p = (const int*)ei;
            s = p[e]; d = p[N_EDGES + e];
        }
        if ((unsigned)s >= N_NODES) s = 0;
        if ((unsigned)d >= N_NODES) d = 0;
    } else {
        s = e - N_EDGES; d = s;
    }
}

// -------- K0: init scratch --------
__global__ void k_init() {
    int i = blockIdx.x * blockDim.x + threadIdx.x;
    int stride = gridDim.x * blockDim.x;
    for (int j = i; j < N_NODES * H1; j += stride) g_d1[j] = 0.0f;
    for (int j = i; j < N_NODES * F1; j += stride) g_o1[j] = 0.0f;
    for (int j = i; j < N_NODES; j += stride)      g_d2[j] = 0.0f;
}

// -------- K1: h1 = x @ W1 ; a_src1/a_dst1 per node --------
// 240 threads = 3 nodes x 80 outputs; W1 column in registers; grid-stride.
__global__ __launch_bounds__(240) void k_gemm1(
        const float* __restrict__ x, const float* __restrict__ W1,
        const float* __restrict__ att_src1, const float* __restrict__ att_dst1) {
    int t  = threadIdx.x % 80;   // output feature (h*8+c)
    int ny = threadIdx.x / 80;   // node slot 0..2
    float w[IN_F];
    #pragma unroll
    for (int k = 0; k < IN_F; k++) w[k] = W1[k * F1 + t];
    float a_s = att_src1[t], a_d = att_dst1[t];
    __shared__ float xs[3][IN_F + 1];
    __shared__ float ps[3][F1], pd[3][F1];
    for (int base = blockIdx.x * 3; base < N_NODES; base += gridDim.x * 3) {
        int n = base + ny;
        if (n < N_NODES && t < IN_F) xs[ny][t] = x[n * IN_F + t];
        __syncthreads();
        if (n < N_NODES) {
            float acc = 0.0f;
            #pragma unroll
            for (int k = 0; k < IN_F; k++) acc = fmaf(xs[ny][k], w[k], acc);
            g_h1[n * F1 + t] = acc;
            ps[ny][t] = acc * a_s;
            pd[ny][t] = acc * a_d;
        }
        __syncthreads();
        if (n < N_NODES && t < H1) {
            float ss = 0.0f, sd = 0.0f;
            #pragma unroll
            for (int c = 0; c < C1; c++) { ss += ps[ny][t * C1 + c]; sd += pd[ny][t * C1 + c]; }
            g_as1[n * H1 + t] = ss;
            g_ad1[n * H1 + t] = sd;
        }
        __syncthreads();
    }
}

// -------- K2: layer1 exp + denom accumulate (no max pass; shift-invariant) --------
__global__ void k_sum1(const void* __restrict__ ei) {
    long long tid = (long long)blockIdx.x * blockDim.x + threadIdx.x;
    if (tid >= EH_TOT) return;
    int e = (int)(tid / H1), h = (int)(tid % H1);
    int s, d; edge_sd(ei, e, s, d);
    float ev = lrelu(g_as1[s * H1 + h] + g_ad1[d * H1 + h]);
    float ex = __expf(ev);
    g_ex[tid] = ex;
    atomicAdd(&g_d1[d * H1 + h], ex);
}

// -------- K3: layer1 message scatter (thread per edge-head, vector red) --------
__global__ void k_msg1(const void* __restrict__ ei) {
    long long tid = (long long)blockIdx.x * blockDim.x + threadIdx.x;
    if (tid >= EH_TOT) return;
    int e = (int)(tid / H1), h = (int)(tid % H1);
    int s, d; edge_sd(ei, e, s, d);
    float alpha = g_ex[tid] / g_d1[d * H1 + h];
    const float4* hp = (const float4*)&g_h1[s * F1 + h * C1];
    float4 v0 = hp[0], v1 = hp[1];
    float* op = &g_o1[d * F1 + h * C1];
    redAdd4(op,     v0.x * alpha, v0.y * alpha, v0.z * alpha, v0.w * alpha);
    redAdd4(op + 4, v1.x * alpha, v1.y * alpha, v1.z * alpha, v1.w * alpha);
}

// -------- K4: bias + ELU + layer2 GEMV (80->1) + a_src2/a_dst2 + init out --------
__global__ void k_layer2_prep(const float* __restrict__ b1, const float* __restrict__ W2,
                              const float* __restrict__ att_src2, const float* __restrict__ att_dst2,
                              const float* __restrict__ b2, float* __restrict__ out) {
    int warp = (blockIdx.x * blockDim.x + threadIdx.x) >> 5;
    int lane = threadIdx.x & 31;
    if (warp >= N_NODES) return;
    float acc = 0.0f;
    #pragma unroll
    for (int i = 0; i < 3; i++) {
        int f = lane + 32 * i;
        if (f < F1) {
            float v = g_o1[warp * F1 + f] + b1[f];
            v = v > 0.0f ? v : (__expf(v) - 1.0f);   // ELU
            acc = fmaf(v, W2[f], acc);
        }
    }
    #pragma unroll
    for (int o = 16; o > 0; o >>= 1) acc += __shfl_down_sync(0xffffffffu, acc, o);
    if (lane == 0) {
        g_h2[warp]  = acc;
        g_as2[warp] = acc * att_src2[0];
        g_ad2[warp] = acc * att_dst2[0];
        out[warp]   = b2[0];
    }
}

// -------- K5: layer2 exp + denom (no max) --------
__global__ void k_sum2(const void* __restrict__ ei) {
    int e = blockIdx.x * blockDim.x + threadIdx.x;
    if (e >= E_TOT) return;
    int s, d; edge_sd(ei, e, s, d);
    float ex = __expf(lrelu(g_as2[s] + g_ad2[d]));
    g_ex[e] = ex;
    atomicAdd(&g_d2[d], ex);
}

// -------- K6: layer2 message scatter --------
__global__ void k_msg2(const void* __restrict__ ei, float* __restrict__ out) {
    int e = blockIdx.x * blockDim.x + threadIdx.x;
    if (e >= E_TOT) return;
    int s, d; edge_sd(ei, e, s, d);
    float alpha = g_ex[e] / g_d2[d];
    atomicAdd(&out[d], g_h2[s] * alpha);
}

extern "C" void kernel_launch(void* const* d_in, const int* in_sizes, int n_in,
                              void* d_out, int out_size) {
    const float* x    = (const float*)d_in[0];
    const void*  ei   = d_in[1];
    const float* W1   = (const float*)d_in[2];
    const float* as1  = (const float*)d_in[3];
    const float* ad1  = (const float*)d_in[4];
    const float* b1   = (const float*)d_in[5];
    const float* W2   = (const float*)d_in[6];
    const float* as2  = (const float*)d_in[7];
    const float* ad2  = (const float*)d_in[8];
    const float* b2   = (const float*)d_in[9];
    float* out = (float*)d_out;

    k_detect<<<1, 32>>>((const int*)ei);
    k_init<<<1184, 256>>>();
    k_gemm1<<<296, 240>>>(x, W1, as1, ad1);

    int blk_eh = (int)((EH_TOT + 255) / 256);
    k_sum1<<<blk_eh, 256>>>(ei);
    k_msg1<<<blk_eh, 256>>>(ei);

    int blk_n = (N_NODES * 32 + 255) / 256;
    k_layer2_prep<<<blk_n, 256>>>(b1, W2, as2, ad2, b2, out);

    int blk_e = (E_TOT + 255) / 256;
    k_sum2<<<blk_e, 256>>>(ei);
    k_msg2<<<blk_e, 256>>>(ei, out);
}

// round 4
// speedup vs baseline: 2.8262x; 1.1482x over previous
#include <cuda_runtime.h>
#include <cuda_bf16.h>
#include <math.h>

// Problem constants
#define N_NODES 100000
#define N_EDGES 1600000
#define E_TOT   (N_EDGES + N_NODES)   // with self loops
#define IN_F    67
#define H1      10
#define C1      8
#define F1      (H1 * C1)             // 80

#define SCAN_B  512
#define SCAN_NB ((N_NODES + SCAN_B - 1) / SCAN_B)   // 196

// -------- scratch (static device globals; no allocation) --------
__device__ float g_h1[N_NODES * F1];     // layer1 transformed features
__device__ float g_as1[N_NODES * H1];    // a_src layer1
__device__ float g_ad1[N_NODES * H1];    // a_dst layer1
__device__ float g_o1[N_NODES * F1];     // layer1 output (normalized, pre-bias)
__device__ float g_h2[N_NODES];          // layer2 transformed (scalar)
__device__ float g_as2[N_NODES];
__device__ float g_ad2[N_NODES];
__device__ int   g_deg[N_NODES];         // per-dst degree
__device__ int   g_row[N_NODES + 1];     // CSR row offsets
__device__ int   g_part[SCAN_NB];        // scan partials
__device__ int   g_cursor[N_NODES];      // scatter cursors
__device__ int   g_csr_src[E_TOT];       // src ids sorted by dst
__device__ int   g_is64;                 // edge_index dtype flag

__device__ __forceinline__ float lrelu(float x) { return x > 0.0f ? x : 0.2f * x; }

// -------- detect edge_index dtype (int64 vs int32) --------
__global__ void k_detect(const int* __restrict__ ei32) {
    if (threadIdx.x == 0 && blockIdx.x == 0) {
        bool is64 = true;
        #pragma unroll
        for (int i = 1; i < 16; i += 2) if (ei32[i] != 0) is64 = false;
        g_is64 = is64 ? 1 : 0;
    }
}

__device__ __forceinline__ void edge_sd(const void* __restrict__ ei, int e, int& s, int& d) {
    if (e < N_EDGES) {
        if (g_is64) {
            const long long* p = (const long long*)ei;
            s = (int)p[e]; d = (int)p[N_EDGES + e];
        } else {
            const int* p = (const int*)ei;
            s = p[e]; d = p[N_EDGES + e];
        }
        if ((unsigned)s >= N_NODES) s = 0;
        if ((unsigned)d >= N_NODES) d = 0;
    } else {
        s = e - N_EDGES; d = s;
    }
}

// -------- CSR build --------
__global__ void k_zero() {
    int i = blockIdx.x * blockDim.x + threadIdx.x;
    if (i < N_NODES) { g_deg[i] = 0; g_cursor[i] = 0; }
}

__global__ void k_hist(const void* __restrict__ ei) {
    int e = blockIdx.x * blockDim.x + threadIdx.x;
    if (e >= E_TOT) return;
    int s, d; edge_sd(ei, e, s, d);
    atomicAdd(&g_deg[d], 1);
}

__global__ void k_scan1() {
    __shared__ int sm[SCAN_B];
    int tid = threadIdx.x;
    int i = blockIdx.x * SCAN_B + tid;
    int v = (i < N_NODES) ? g_deg[i] : 0;
    sm[tid] = v;
    __syncthreads();
    #pragma unroll
    for (int off = 1; off < SCAN_B; off <<= 1) {
        int add = (tid >= off) ? sm[tid - off] : 0;
        __syncthreads();
        sm[tid] += add;
        __syncthreads();
    }
    if (i < N_NODES) g_row[i] = sm[tid] - v;   // exclusive
    if (tid == SCAN_B - 1) g_part[blockIdx.x] = sm[tid];
}

__global__ void k_scan2() {
    if (threadIdx.x == 0) {
        int running = 0;
        for (int b = 0; b < SCAN_NB; b++) {
            int t = g_part[b];
            g_part[b] = running;
            running += t;
        }
        g_row[N_NODES] = running;   // == E_TOT
    }
}

__global__ void k_scan3() {
    int i = blockIdx.x * SCAN_B + threadIdx.x;
    if (i < N_NODES) g_row[i] += g_part[blockIdx.x];
}

__global__ void k_scatter(const void* __restrict__ ei) {
    int e = blockIdx.x * blockDim.x + threadIdx.x;
    if (e >= E_TOT) return;
    int s, d; edge_sd(ei, e, s, d);
    int pos = atomicAdd(&g_cursor[d], 1);
    g_csr_src[g_row[d] + pos] = s;
}

// -------- K1: h1 = x @ W1 ; a_src1/a_dst1 per node --------
__global__ __launch_bounds__(240) void k_gemm1(
        const float* __restrict__ x, const float* __restrict__ W1,
        const float* __restrict__ att_src1, const float* __restrict__ att_dst1) {
    int t  = threadIdx.x % 80;
    int ny = threadIdx.x / 80;
    float w[IN_F];
    #pragma unroll
    for (int k = 0; k < IN_F; k++) w[k] = W1[k * F1 + t];
    float a_s = att_src1[t], a_d = att_dst1[t];
    __shared__ float xs[3][IN_F + 1];
    __shared__ float ps[3][F1], pd[3][F1];
    for (int base = blockIdx.x * 3; base < N_NODES; base += gridDim.x * 3) {
        int n = base + ny;
        if (n < N_NODES && t < IN_F) xs[ny][t] = x[n * IN_F + t];
        __syncthreads();
        if (n < N_NODES) {
            float acc = 0.0f;
            #pragma unroll
            for (int k = 0; k < IN_F; k++) acc = fmaf(xs[ny][k], w[k], acc);
            g_h1[n * F1 + t] = acc;
            ps[ny][t] = acc * a_s;
            pd[ny][t] = acc * a_d;
        }
        __syncthreads();
        if (n < N_NODES && t < H1) {
            float ss = 0.0f, sd = 0.0f;
            #pragma unroll
            for (int c = 0; c < C1; c++) { ss += ps[ny][t * C1 + c]; pd[ny][t * C1 + c], sd += pd[ny][t * C1 + c]; }
            g_as1[n * H1 + t] = ss;
            g_ad1[n * H1 + t] = sd;
        }
        __syncthreads();
    }
}

// -------- K2: fused layer1 softmax+aggregate, block(80) per dst node --------
#define UNROLL_E 4
__global__ __launch_bounds__(80) void k_edge1() {
    int d = blockIdx.x;
    int t = threadIdx.x;          // feature index 0..79
    int h = t >> 3;               // head 0..9
    __shared__ float s_ex[UNROLL_E][H1];
    __shared__ int   s_src[UNROLL_E];
    __shared__ float s_den[H1];
    int r0 = g_row[d], r1 = g_row[d + 1];
    float acc = 0.0f, den = 0.0f;
    for (int j = r0; j < r1; j += UNROLL_E) {
        int m = min(UNROLL_E, r1 - j);
        if (t < m * H1) {
            int q = t / H1, hh = t - q * H1;
            int s = g_csr_src[j + q];
            if (hh == 0) s_src[q] = s;
            float ev = lrelu(g_as1[s * H1 + hh] + g_ad1[d * H1 + hh]);
            s_ex[q][hh] = __expf(ev);
        }
        __syncthreads();
        #pragma unroll
        for (int q = 0; q < UNROLL_E; q++) {
            if (q < m) {
                int s = s_src[q];
                acc = fmaf(s_ex[q][h], g_h1[s * F1 + t], acc);
            }
        }
        if (t < H1) {
            #pragma unroll
            for (int q = 0; q < UNROLL_E; q++)
                if (q < m) den += s_ex[q][t];
        }
        __syncthreads();
    }
    if (t < H1) s_den[t] = den;
    __syncthreads();
    g_o1[d * F1 + t] = acc / s_den[h];
}

// -------- K3: bias + ELU + layer2 GEMV (80->1) + a_src2/a_dst2 --------
__global__ void k_layer2_prep(const float* __restrict__ b1, const float* __restrict__ W2,
                              const float* __restrict__ att_src2, const float* __restrict__ att_dst2) {
    int warp = (blockIdx.x * blockDim.x + threadIdx.x) >> 5;
    int lane = threadIdx.x & 31;
    if (warp >= N_NODES) return;
    float acc = 0.0f;
    #pragma unroll
    for (int i = 0; i < 3; i++) {
        int f = lane + 32 * i;
        if (f < F1) {
            float v = g_o1[warp * F1 + f] + b1[f];
            v = v > 0.0f ? v : (__expf(v) - 1.0f);   // ELU
            acc = fmaf(v, W2[f], acc);
        }
    }
    #pragma unroll
    for (int o = 16; o > 0; o >>= 1) acc += __shfl_down_sync(0xffffffffu, acc, o);
    if (lane == 0) {
        g_h2[warp]  = acc;
        g_as2[warp] = acc * att_src2[0];
        g_ad2[warp] = acc * att_dst2[0];
    }
}

// -------- K4: fused layer2 softmax+aggregate, warp per dst node --------
__global__ void k_edge2(const float* __restrict__ b2, float* __restrict__ out) {
    int d    = (blockIdx.x * blockDim.x + threadIdx.x) >> 5;
    int lane = threadIdx.x & 31;
    if (d >= N_NODES) return;
    int r0 = g_row[d], r1 = g_row[d + 1];
    float ad = g_ad2[d];
    float num = 0.0f, den = 0.0f;
    for (int j = r0 + lane; j < r1; j += 32) {
        int s = g_csr_src[j];
        float ex = __expf(lrelu(g_as2[s] + ad));
        num = fmaf(ex, g_h2[s], num);
        den += ex;
    }
    #pragma unroll
    for (int o = 16; o > 0; o >>= 1) {
        num += __shfl_down_sync(0xffffffffu, num, o);
        den += __shfl_down_sync(0xffffffffu, den, o);
    }
    if (lane == 0) out[d] = num / den + b2[0];
}

extern "C" void kernel_launch(void* const* d_in, const int* in_sizes, int n_in,
                              void* d_out, int out_size) {
    const float* x    = (const float*)d_in[0];
    const void*  ei   = d_in[1];
    const float* W1   = (const float*)d_in[2];
    const float* as1  = (const float*)d_in[3];
    const float* ad1  = (const float*)d_in[4];
    const float* b1   = (const float*)d_in[5];
    const float* W2   = (const float*)d_in[6];
    const float* as2  = (const float*)d_in[7];
    const float* ad2  = (const float*)d_in[8];
    const float* b2   = (const float*)d_in[9];
    float* out = (float*)d_out;

    int blk_e = (E_TOT + 255) / 256;

    k_detect<<<1, 32>>>((const int*)ei);
    k_zero<<<(N_NODES + 255) / 256, 256>>>();
    k_hist<<<blk_e, 256>>>(ei);
    k_scan1<<<SCAN_NB, SCAN_B>>>();
    k_scan2<<<1, 32>>>();
    k_scan3<<<SCAN_NB, SCAN_B>>>();
    k_scatter<<<blk_e, 256>>>(ei);

    k_gemm1<<<296, 240>>>(x, W1, as1, ad1);
    k_edge1<<<N_NODES, 80>>>();

    int blk_n = (N_NODES * 32 + 255) / 256;
    k_layer2_prep<<<blk_n, 256>>>(b1, W2, as2, ad2);
    k_edge2<<<blk_n, 256>>>(b2, out);
}

// round 5
// speedup vs baseline: 3.0182x; 1.0679x over previous
#include <cuda_runtime.h>
#include <cuda_bf16.h>
#include <math.h>

// Problem constants
#define N_NODES 100000
#define N_EDGES 1600000
#define E_TOT   (N_EDGES + N_NODES)   // with self loops
#define IN_F    67
#define H1      10
#define C1      8
#define F1      (H1 * C1)             // 80

#define SCAN_B  512
#define SCAN_NB ((N_NODES + SCAN_B - 1) / SCAN_B)   // 196

#define HIST_BLOCKS ((E_TOT + 255) / 256)           // 6641
#define GEMM_BLOCKS 296

// -------- scratch (static device globals; no allocation) --------
__device__ float g_h1[N_NODES * F1];     // layer1 transformed features
__device__ float g_as1[N_NODES * H1];    // a_src layer1
__device__ float g_ad1[N_NODES * H1];    // a_dst layer1
__device__ float g_o1[N_NODES * F1];     // layer1 output (normalized, pre-bias)
__device__ float g_h2[N_NODES];          // layer2 transformed (scalar)
__device__ float g_as2[N_NODES];
__device__ float g_ad2[N_NODES];
__device__ int   g_deg[N_NODES];         // per-dst degree
__device__ int   g_row[N_NODES + 1];     // CSR row offsets
__device__ int   g_part[SCAN_NB];        // scan partials
__device__ int   g_cursor[N_NODES];      // scatter cursors (init = row offsets)
__device__ int   g_csr_src[E_TOT];       // src ids sorted by dst
__device__ int   g_is64;                 // edge_index dtype flag

__device__ __forceinline__ float lrelu(float x) { return x > 0.0f ? x : 0.2f * x; }

__device__ __forceinline__ void edge_sd(const void* __restrict__ ei, int e, int& s, int& d) {
    if (e < N_EDGES) {
        if (g_is64) {
            const long long* p = (const long long*)ei;
            s = (int)p[e]; d = (int)p[N_EDGES + e];
        } else {
            const int* p = (const int*)ei;
            s = p[e]; d = p[N_EDGES + e];
        }
        if ((unsigned)s >= N_NODES) s = 0;
        if ((unsigned)d >= N_NODES) d = 0;
    } else {
        s = e - N_EDGES; d = s;
    }
}

// -------- L0: detect dtype + zero degrees --------
__global__ void k_init(const int* __restrict__ ei32) {
    int i = blockIdx.x * blockDim.x + threadIdx.x;
    if (i < N_NODES) g_deg[i] = 0;
    if (i == 0) {
        bool is64 = true;
        #pragma unroll
        for (int k = 1; k < 16; k += 2) if (ei32[k] != 0) is64 = false;
        g_is64 = is64 ? 1 : 0;
    }
}

// -------- L1: fused histogram (blocks [0,HIST_BLOCKS)) + gemm1 (rest) --------
__global__ __launch_bounds__(256) void k_hist_gemm(
        const void* __restrict__ ei,
        const float* __restrict__ x, const float* __restrict__ W1,
        const float* __restrict__ att_src1, const float* __restrict__ att_dst1) {
    if (blockIdx.x < HIST_BLOCKS) {
        int e = blockIdx.x * 256 + threadIdx.x;
        if (e < E_TOT) {
            int s, d; edge_sd(ei, e, s, d);
            atomicAdd(&g_deg[d], 1);
        }
        return;
    }
    // ---- gemm part: 240 active threads = 3 nodes x 80 outputs ----
    int bid = blockIdx.x - HIST_BLOCKS;
    if (threadIdx.x >= 240) return;
    int t  = threadIdx.x % 80;
    int ny = threadIdx.x / 80;
    float w[IN_F];
    #pragma unroll
    for (int k = 0; k < IN_F; k++) w[k] = W1[k * F1 + t];
    float a_s = att_src1[t], a_d = att_dst1[t];
    __shared__ float xs[3][IN_F + 1];
    __shared__ float ps[3][F1], pd[3][F1];
    for (int base = bid * 3; base < N_NODES; base += GEMM_BLOCKS * 3) {
        int n = base + ny;
        if (n < N_NODES && t < IN_F) xs[ny][t] = x[n * IN_F + t];
        __syncthreads();
        if (n < N_NODES) {
            float acc = 0.0f;
            #pragma unroll
            for (int k = 0; k < IN_F; k++) acc = fmaf(xs[ny][k], w[k], acc);
            g_h1[n * F1 + t] = acc;
            ps[ny][t] = acc * a_s;
            pd[ny][t] = acc * a_d;
        }
        __syncthreads();
        if (n < N_NODES && t < H1) {
            float ss = 0.0f, sd = 0.0f;
            #pragma unroll
            for (int c = 0; c < C1; c++) { ss += ps[ny][t * C1 + c]; sd += pd[ny][t * C1 + c]; }
            g_as1[n * H1 + t] = ss;
            g_ad1[n * H1 + t] = sd;
        }
        __syncthreads();
    }
}

// -------- L2: per-block exclusive scan of degrees --------
__global__ void k_scan1() {
    __shared__ int sm[SCAN_B];
    int tid = threadIdx.x;
    int i = blockIdx.x * SCAN_B + tid;
    int v = (i < N_NODES) ? g_deg[i] : 0;
    sm[tid] = v;
    __syncthreads();
    #pragma unroll
    for (int off = 1; off < SCAN_B; off <<= 1) {
        int add = (tid >= off) ? sm[tid - off] : 0;
        __syncthreads();
        sm[tid] += add;
        __syncthreads();
    }
    if (i < N_NODES) g_row[i] = sm[tid] - v;   // exclusive within block
    if (tid == SCAN_B - 1) g_part[blockIdx.x] = sm[tid];
}

// -------- L3: add block prefixes (each block re-derives its prefix) + cursor init --------
__global__ void k_scan23() {
    __shared__ int sp[SCAN_NB];
    __shared__ int pref_s;
    int b = blockIdx.x, t = threadIdx.x;
    if (t < SCAN_NB) sp[t] = g_part[t];
    __syncthreads();
    if (t == 0) {
        int p = 0;
        for (int i = 0; i < b; i++) p += sp[i];
        pref_s = p;
    }
    __syncthreads();
    int pref = pref_s;
    int i = b * SCAN_B + t;
    if (i < N_NODES) {
        int v = g_row[i] + pref;
        g_row[i] = v;
        g_cursor[i] = v;
    }
    if (b == SCAN_NB - 1 && t == 0) g_row[N_NODES] = pref + sp[b];
}

// -------- L4: scatter src ids into CSR --------
__global__ void k_scatter(const void* __restrict__ ei) {
    int e = blockIdx.x * blockDim.x + threadIdx.x;
    if (e >= E_TOT) return;
    int s, d; edge_sd(ei, e, s, d);
    int pos = atomicAdd(&g_cursor[d], 1);
    g_csr_src[pos] = s;
}

// -------- L5: fused layer1 softmax+aggregate, block(80) per dst node --------
#define UNROLL_E 8
__global__ __launch_bounds__(80) void k_edge1() {
    int d = blockIdx.x;
    int t = threadIdx.x;          // feature index 0..79
    int h = t >> 3;               // head 0..9
    __shared__ float s_ex[UNROLL_E][H1];
    __shared__ int   s_src[UNROLL_E];
    __shared__ float s_ad[H1];
    __shared__ float s_den[H1];
    if (t < H1) s_ad[t] = g_ad1[d * H1 + t];
    int r0 = g_row[d], r1 = g_row[d + 1];
    float acc = 0.0f, den = 0.0f;
    __syncthreads();
    for (int j = r0; j < r1; j += UNROLL_E) {
        int m = min(UNROLL_E, r1 - j);
        {   // t in [0, m*10): q-th edge, hh-th head  (m*10 <= 80)
            int q = t / H1, hh = t - q * H1;
            if (q < m) {
                int s = g_csr_src[j + q];
                if (hh == 0) s_src[q] = s;
                float ev = lrelu(g_as1[s * H1 + hh] + s_ad[hh]);
                s_ex[q][hh] = __expf(ev);
            }
        }
        __syncthreads();
        #pragma unroll
        for (int q = 0; q < UNROLL_E; q++) {
            if (q < m) {
                int s = s_src[q];
                acc = fmaf(s_ex[q][h], g_h1[s * F1 + t], acc);
            }
        }
        if (t < H1) {
            #pragma unroll
            for (int q = 0; q < UNROLL_E; q++)
                if (q < m) den += s_ex[q][t];
        }
        __syncthreads();
    }
    if (t < H1) s_den[t] = den;
    __syncthreads();
    g_o1[d * F1 + t] = acc / s_den[h];
}

// -------- L6: bias + ELU + layer2 GEMV (80->1) + a_src2/a_dst2 --------
__global__ void k_layer2_prep(const float* __restrict__ b1, const float* __restrict__ W2,
                              const float* __restrict__ att_src2, const float* __restrict__ att_dst2) {
    int warp = (blockIdx.x * blockDim.x + threadIdx.x) >> 5;
    int lane = threadIdx.x & 31;
    if (warp >= N_NODES) return;
    float acc = 0.0f;
    #pragma unroll
    for (int i = 0; i < 3; i++) {
        int f = lane + 32 * i;
        if (f < F1) {
            float v = g_o1[warp * F1 + f] + b1[f];
            v = v > 0.0f ? v : (__expf(v) - 1.0f);   // ELU
            acc = fmaf(v, W2[f], acc);
        }
    }
    #pragma unroll
    for (int o = 16; o > 0; o >>= 1) acc += __shfl_down_sync(0xffffffffu, acc, o);
    if (lane == 0) {
        g_h2[warp]  = acc;
        g_as2[warp] = acc * att_src2[0];
        g_ad2[warp] = acc * att_dst2[0];
    }
}

// -------- L7: fused layer2 softmax+aggregate, warp per dst node --------
__global__ void k_edge2(const float* __restrict__ b2, float* __restrict__ out) {
    int d    = (blockIdx.x * blockDim.x + threadIdx.x) >> 5;
    int lane = threadIdx.x & 31;
    if (d >= N_NODES) return;
    int r0 = g_row[d], r1 = g_row[d + 1];
    float ad = g_ad2[d];
    float num = 0.0f, den = 0.0f;
    for (int j = r0 + lane; j < r1; j += 32) {
        int s = g_csr_src[j];
        float ex = __expf(lrelu(g_as2[s] + ad));
        num = fmaf(ex, g_h2[s], num);
        den += ex;
    }
    #pragma unroll
    for (int o = 16; o > 0; o >>= 1) {
        num += __shfl_down_sync(0xffffffffu, num, o);
        den += __shfl_down_sync(0xffffffffu, den, o);
    }
    if (lane == 0) out[d] = num / den + b2[0];
}

extern "C" void kernel_launch(void* const* d_in, const int* in_sizes, int n_in,
                              void* d_out, int out_size) {
    const float* x    = (const float*)d_in[0];
    const void*  ei   = d_in[1];
    const float* W1   = (const float*)d_in[2];
    const float* as1  = (const float*)d_in[3];
    const float* ad1  = (const float*)d_in[4];
    const float* b1   = (const float*)d_in[5];
    const float* W2   = (const float*)d_in[6];
    const float* as2  = (const float*)d_in[7];
    const float* ad2  = (const float*)d_in[8];
    const float* b2   = (const float*)d_in[9];
    float* out = (float*)d_out;

    k_init<<<(N_NODES + 255) / 256, 256>>>((const int*)ei);              // 0
    k_hist_gemm<<<HIST_BLOCKS + GEMM_BLOCKS, 256>>>(ei, x, W1, as1, ad1); // 1
    k_scan1<<<SCAN_NB, SCAN_B>>>();                                       // 2
    k_scan23<<<SCAN_NB, SCAN_B>>>();                                      // 3
    k_scatter<<<HIST_BLOCKS, 256>>>(ei);                                  // 4
    k_edge1<<<N_NODES, 80>>>();                                           // 5  <- profiled
    int blk_n = (N_NODES * 32 + 255) / 256;
    k_layer2_prep<<<blk_n, 256>>>(b1, W2, as2, ad2);                      // 6
    k_edge2<<<blk_n, 256>>>(b2, out);                                     // 7
}